// round 1
// baseline (speedup 1.0000x reference)
#include <cuda_runtime.h>

// HDTBLUT: 4 LUT kernels (h,d,t,b) x 4 rotations, 2x upscale, reflect pad.
// One thread per LR pixel. All rotations computed in original coordinates:
//   r0 tap: ( y+dy,       x+dx      )
//   r1 tap: ( y+dx,      |x-dy|     )
//   r2 tap: (|y-dy|,     |x-dx|     )
//   r3 tap: (|y-dx|, reflHi(x+dy)   )
// Output 2x2 block permutation per rotation folded into final combine.

#define NN    1024
#define OW    2048
#define TX    32
#define TY    8
#define PITCH 38          // TX + 6
#define SROWS 14          // TY + 6

__device__ __forceinline__ void addx2(unsigned long long &a, unsigned long long b) {
    asm("add.rn.f32x2 %0, %0, %1;" : "+l"(a) : "l"(b));
}
__device__ __forceinline__ float lo32(unsigned long long s) {
    return __uint_as_float((unsigned int)s);
}
__device__ __forceinline__ float hi32(unsigned long long s) {
    return __uint_as_float((unsigned int)(s >> 32));
}

__global__ __launch_bounds__(256)
void lut4_kernel(const int* __restrict__ img,
                 const ulonglong2* __restrict__ wh,
                 const ulonglong2* __restrict__ wd,
                 const ulonglong2* __restrict__ wt,
                 const ulonglong2* __restrict__ wb,
                 float* __restrict__ out)
{
    __shared__ int tile[SROWS * PITCH];
    const int tx = threadIdx.x, ty = threadIdx.y;
    const int x0 = blockIdx.x * TX, y0 = blockIdx.y * TY;
    const int* ib = img + (size_t)blockIdx.z * (NN * NN);

    // Fill tile with reflect padding applied at global image edges.
    for (int i = ty * TX + tx; i < SROWS * PITCH; i += TX * TY) {
        int ry = i / PITCH, rx = i - ry * PITCH;
        int gy = y0 - 3 + ry, gx = x0 - 3 + rx;
        gy = gy < 0 ? -gy : (gy >= NN ? 2 * NN - 2 - gy : gy);
        gx = gx < 0 ? -gx : (gx >= NN ? 2 * NN - 2 - gx : gx);
        tile[i] = __ldg(&ib[gy * NN + gx]);
    }
    __syncthreads();

    const int* sp = &tile[(ty + 3) * PITCH + (tx + 3)];
    const int A = sp[0] << 12;   // center tap * 4096, shared by all 16 indices

    // Per-rotation packed accumulators: (w0,w1) in *l, (w2,w3) in *h
    unsigned long long s0l = 0, s0h = 0, s1l = 0, s1h = 0;
    unsigned long long s2l = 0, s2h = 0, s3l = 0, s3h = 0;

    // Rotated smem offsets (compile-time constants)
#define OFF0(dy, dx) ( (dy) * PITCH + (dx))
#define OFF1(dy, dx) ( (dx) * PITCH - (dy))
#define OFF2(dy, dx) (-(dy) * PITCH - (dx))
#define OFF3(dy, dx) (-(dx) * PITCH + (dy))

#define G(W, OFF, y1, x1, y2, x2, y3, x3) \
    __ldg(&W[A + sp[OFF(y1, x1)] * 256 + sp[OFF(y2, x2)] * 16 + sp[OFF(y3, x3)]])

#define PASS(W, y1, x1, y2, x2, y3, x3) { \
    ulonglong2 g; \
    g = G(W, OFF0, y1, x1, y2, x2, y3, x3); addx2(s0l, g.x); addx2(s0h, g.y); \
    g = G(W, OFF1, y1, x1, y2, x2, y3, x3); addx2(s1l, g.x); addx2(s1h, g.y); \
    g = G(W, OFF2, y1, x1, y2, x2, y3, x3); addx2(s2l, g.x); addx2(s2h, g.y); \
    g = G(W, OFF3, y1, x1, y2, x2, y3, x3); addx2(s3l, g.x); addx2(s3h, g.y); }

    PASS(wh, 0, 1, 0, 2, 0, 3);   // h: (0,0),(0,1),(0,2),(0,3)
    PASS(wd, 1, 1, 2, 2, 3, 3);   // d: (0,0),(1,1),(2,2),(3,3)
    PASS(wt, 2, 1, 3, 1, 3, 2);   // t: (0,0),(2,1),(3,1),(3,2)
    PASS(wb, 1, 2, 1, 3, 2, 3);   // b: (0,0),(1,2),(1,3),(2,3)

#undef PASS
#undef G
#undef OFF0
#undef OFF1
#undef OFF2
#undef OFF3

    const float S0x = lo32(s0l), S0y = hi32(s0l), S0z = lo32(s0h), S0w = hi32(s0h);
    const float S1x = lo32(s1l), S1y = hi32(s1l), S1z = lo32(s1h), S1w = hi32(s1h);
    const float S2x = lo32(s2l), S2y = hi32(s2l), S2z = lo32(s2h), S2w = hi32(s2h);
    const float S3x = lo32(s3l), S3y = hi32(s3l), S3z = lo32(s3h), S3w = hi32(s3h);

    // Inverse-rotation permutation of the 2x2 block, then /4
    const float a00 = (S0x + S1z + S2w + S3y) * 0.25f;
    const float a01 = (S0y + S1x + S2z + S3w) * 0.25f;
    const float a10 = (S0z + S1w + S2y + S3x) * 0.25f;
    const float a11 = (S0w + S1y + S2x + S3z) * 0.25f;

    float* ob = out + (size_t)blockIdx.z * ((size_t)OW * OW)
                    + (size_t)(2 * (y0 + ty)) * OW + 2 * (x0 + tx);
    *(float2*)(ob)      = make_float2(a00, a01);
    *(float2*)(ob + OW) = make_float2(a10, a11);
}

extern "C" void kernel_launch(void* const* d_in, const int* in_sizes, int n_in,
                              void* d_out, int out_size) {
    (void)n_in; (void)out_size;
    const int* img = (const int*)d_in[0];
    const int B = in_sizes[0] / (NN * NN);
    dim3 blk(TX, TY, 1);
    dim3 grd(NN / TX, NN / TY, B);
    lut4_kernel<<<grd, blk>>>(img,
                              (const ulonglong2*)d_in[1],
                              (const ulonglong2*)d_in[2],
                              (const ulonglong2*)d_in[3],
                              (const ulonglong2*)d_in[4],
                              (float*)d_out);
}

// round 2
// speedup vs baseline: 1.0548x; 1.0548x over previous
#include <cuda_runtime.h>

// HDTBLUT: 4 LUT kernels (h,d,t,b) x 4 rotations, 2x upscale, reflect pad.
// R2: pixel values are 4-bit; pack tile rows as nibbles in smem so every
// 16-bit LUT index is extracted from two 64-bit row registers with
// constant shifts. Cuts LDS wavefronts from ~49/warp to ~14/warp
// (kernel is L1tex-wavefront bound).

#define NN     1024
#define OW     2048
#define TX     32
#define TY     8
#define SPITCH 40          // staging pitch in ints (160B, 16B-aligned rows)
#define SROWS  14          // TY + 6
#define PW     8           // packed words per row (5 used, padded)

__device__ __forceinline__ void addx2(unsigned long long &a, unsigned long long b) {
    asm("add.rn.f32x2 %0, %0, %1;" : "+l"(a) : "l"(b));
}
__device__ __forceinline__ float lo32(unsigned long long s) {
    return __uint_as_float((unsigned int)s);
}
__device__ __forceinline__ float hi32(unsigned long long s) {
    return __uint_as_float((unsigned int)(s >> 32));
}
// nibble-reverse a 16-bit value: n0n1n2n3 -> n3n2n1n0
__device__ __forceinline__ unsigned rev16(unsigned w) {
    unsigned s = ((w & 0x0F0Fu) << 4) | ((w >> 4) & 0x0F0Fu);
    return ((s & 0xFFu) << 8) | (s >> 8);
}

__global__ __launch_bounds__(256)
void lut4_kernel(const int* __restrict__ img,
                 const ulonglong2* __restrict__ wh,
                 const ulonglong2* __restrict__ wd,
                 const ulonglong2* __restrict__ wt,
                 const ulonglong2* __restrict__ wb,
                 float* __restrict__ out)
{
    __shared__ alignas(16) int stage[SROWS * SPITCH];
    __shared__ unsigned int pk[SROWS * PW];

    const int tx = threadIdx.x, ty = threadIdx.y;
    const int tid = ty * TX + tx;
    const int x0 = blockIdx.x * TX, y0 = blockIdx.y * TY;
    const int* ib = img + (size_t)blockIdx.z * (NN * NN);

    // Fill staging tile with reflect padding at global edges.
    for (int i = tid; i < SROWS * SPITCH; i += TX * TY) {
        int ry = i / SPITCH, rx = i - ry * SPITCH;
        int gy = y0 - 3 + ry, gx = x0 - 3 + rx;
        gy = gy < 0 ? -gy : (gy >= NN ? 2 * NN - 2 - gy : gy);
        gx = gx < 0 ? -gx : (gx >= NN ? 2 * NN - 2 - gx : gx);
        stage[i] = __ldg(&ib[gy * NN + gx]);
    }
    __syncthreads();

    // Pack rows: 5 words x 14 rows, big-endian nibbles (pixel c at bits 28-4*(c&7)).
    if (tid < SROWS * 5) {
        int row = tid / 5, w = tid - row * 5;
        const int4* s = (const int4*)&stage[row * SPITCH + 8 * w];
        int4 u0 = s[0], u1 = s[1];
        unsigned word = ((unsigned)u0.x << 28) | ((unsigned)u0.y << 24) |
                        ((unsigned)u0.z << 20) | ((unsigned)u0.w << 16) |
                        ((unsigned)u1.x << 12) | ((unsigned)u1.y << 8)  |
                        ((unsigned)u1.z << 4)  |  (unsigned)u1.w;
        pk[row * PW + w] = word;
    }
    __syncthreads();

    // Load 7 window rows as pre-shifted 64-bit registers.
    // After the shift, window nibble j (tile col tx+j, j=0..6; center j=3)
    // sits at bits [60-4j, 64-4j).
    unsigned long long Q[7];
    const int q = tx >> 3;
    const int off4 = (tx & 7) * 4;
#pragma unroll
    for (int r = 0; r < 7; r++) {
        const unsigned* row = &pk[(ty + r) * PW + q];
        unsigned long long P = ((unsigned long long)row[0] << 32) | row[1];
        Q[r] = P << off4;
    }

#define NIB(r, j) ((unsigned)(Q[r] >> (60 - 4 * (j))) & 0xFu)

    // h rotation 0: nibbles j=3..6 of center row, directly.
    const unsigned iH0 = (unsigned)(Q[3] >> 36) & 0xFFFFu;
    // left window (j=0..3): v(x-3)<<12|v(x-2)<<8|v(x-1)<<4|v(x)
    const unsigned wl  = (unsigned)(Q[3] >> 48) & 0xFFFFu;
    const unsigned iH2 = rev16(wl);
    const unsigned A12 = (wl & 0xFu) << 12;   // center pixel << 12

    const unsigned iH1 = A12 | (NIB(4,3) << 8) | (NIB(5,3) << 4) | NIB(6,3);
    const unsigned iH3 = A12 | (NIB(2,3) << 8) | (NIB(1,3) << 4) | NIB(0,3);

    const unsigned iD0 = A12 | (NIB(4,4) << 8) | (NIB(5,5) << 4) | NIB(6,6);
    const unsigned iD1 = A12 | (NIB(4,2) << 8) | (NIB(5,1) << 4) | NIB(6,0);
    const unsigned iD2 = A12 | (NIB(2,2) << 8) | (NIB(1,1) << 4) | NIB(0,0);
    const unsigned iD3 = A12 | (NIB(2,4) << 8) | (NIB(1,5) << 4) | NIB(0,6);

    const unsigned iT0 = A12 | (NIB(5,4) << 8) | (NIB(6,4) << 4) | NIB(6,5);
    const unsigned iT1 = A12 | (NIB(4,1) << 8) | (NIB(4,0) << 4) | NIB(5,0);
    const unsigned iT2 = A12 | (NIB(1,2) << 8) | (NIB(0,2) << 4) | NIB(0,1);
    const unsigned iT3 = A12 | (NIB(2,5) << 8) | (NIB(2,6) << 4) | NIB(1,6);

    const unsigned iB0 = A12 | (NIB(4,5) << 8) | (NIB(4,6) << 4) | NIB(5,6);
    const unsigned iB1 = A12 | (NIB(5,2) << 8) | (NIB(6,2) << 4) | NIB(6,1);
    const unsigned iB2 = A12 | (NIB(2,1) << 8) | (NIB(2,0) << 4) | NIB(1,0);
    const unsigned iB3 = A12 | (NIB(1,4) << 8) | (NIB(0,4) << 4) | NIB(0,5);

#undef NIB

    // Per-rotation packed accumulators: (w0,w1) in *l, (w2,w3) in *h
    unsigned long long s0l = 0, s0h = 0, s1l = 0, s1h = 0;
    unsigned long long s2l = 0, s2h = 0, s3l = 0, s3h = 0;

#define PASS(W, I0, I1, I2, I3) { ulonglong2 g; \
    g = __ldg(&W[I0]); addx2(s0l, g.x); addx2(s0h, g.y); \
    g = __ldg(&W[I1]); addx2(s1l, g.x); addx2(s1h, g.y); \
    g = __ldg(&W[I2]); addx2(s2l, g.x); addx2(s2h, g.y); \
    g = __ldg(&W[I3]); addx2(s3l, g.x); addx2(s3h, g.y); }

    PASS(wh, iH0, iH1, iH2, iH3)
    PASS(wd, iD0, iD1, iD2, iD3)
    PASS(wt, iT0, iT1, iT2, iT3)
    PASS(wb, iB0, iB1, iB2, iB3)
#undef PASS

    const float S0x = lo32(s0l), S0y = hi32(s0l), S0z = lo32(s0h), S0w = hi32(s0h);
    const float S1x = lo32(s1l), S1y = hi32(s1l), S1z = lo32(s1h), S1w = hi32(s1h);
    const float S2x = lo32(s2l), S2y = hi32(s2l), S2z = lo32(s2h), S2w = hi32(s2h);
    const float S3x = lo32(s3l), S3y = hi32(s3l), S3z = lo32(s3h), S3w = hi32(s3h);

    // Inverse-rotation permutation of the 2x2 block, then /4
    const float a00 = (S0x + S1z + S2w + S3y) * 0.25f;
    const float a01 = (S0y + S1x + S2z + S3w) * 0.25f;
    const float a10 = (S0z + S1w + S2y + S3x) * 0.25f;
    const float a11 = (S0w + S1y + S2x + S3z) * 0.25f;

    float* ob = out + (size_t)blockIdx.z * ((size_t)OW * OW)
                    + (size_t)(2 * (y0 + ty)) * OW + 2 * (x0 + tx);
    *(float2*)(ob)      = make_float2(a00, a01);
    *(float2*)(ob + OW) = make_float2(a10, a11);
}

extern "C" void kernel_launch(void* const* d_in, const int* in_sizes, int n_in,
                              void* d_out, int out_size) {
    (void)n_in; (void)out_size;
    const int* img = (const int*)d_in[0];
    const int B = in_sizes[0] / (NN * NN);
    dim3 blk(TX, TY, 1);
    dim3 grd(NN / TX, NN / TY, B);
    lut4_kernel<<<grd, blk>>>(img,
                              (const ulonglong2*)d_in[1],
                              (const ulonglong2*)d_in[2],
                              (const ulonglong2*)d_in[3],
                              (const ulonglong2*)d_in[4],
                              (float*)d_out);
}